// round 1
// baseline (speedup 1.0000x reference)
#include <cuda_runtime.h>
#include <math.h>

#define NODES_MAX 100000
#define EDGES_MAX 1200000
#define F 64
#define NEG_SLOPE 0.2f

// ---------------- static device scratch (no allocations allowed) -------------
__device__ int   g_counts[NODES_MAX];          // histogram, then scatter cursor
__device__ int   g_rowptr[NODES_MAX + 1];
__device__ int   g_bsums[256];
__device__ int   g_boffs[256];
__device__ int   g_csr[EDGES_MAX + NODES_MAX]; // src index per (dst-sorted) edge
__device__ float g_h[NODES_MAX * F];           // GEMM output (pre-aggregation)
__device__ float g_hagg[NODES_MAX * F];        // post-aggregation activations
__device__ float g_asrc[NODES_MAX];
__device__ float g_adst[NODES_MAX];

// ---------------- CSR build ---------------------------------------------------
__global__ void k_init_counts(int n) {
    int i = blockIdx.x * blockDim.x + threadIdx.x;
    if (i < n) g_counts[i] = 1;   // self loop
}

__global__ void k_count(const int* __restrict__ dst, int e) {
    int i = blockIdx.x * blockDim.x + threadIdx.x;
    if (i < e) atomicAdd(&g_counts[dst[i]], 1);
}

// block-local exclusive scan of counts -> rowptr, block totals -> g_bsums
__global__ void k_scan_block(int n) {
    __shared__ int sh[1024];
    int i = blockIdx.x * 1024 + threadIdx.x;
    int v = (i < n) ? g_counts[i] : 0;
    sh[threadIdx.x] = v;
    __syncthreads();
#pragma unroll
    for (int off = 1; off < 1024; off <<= 1) {
        int t = (threadIdx.x >= off) ? sh[threadIdx.x - off] : 0;
        __syncthreads();
        sh[threadIdx.x] += t;
        __syncthreads();
    }
    if (i < n) g_rowptr[i] = sh[threadIdx.x] - v;   // exclusive
    if (threadIdx.x == 1023) g_bsums[blockIdx.x] = sh[1023];
}

__global__ void k_scan_sums(int nb) {
    if (threadIdx.x == 0 && blockIdx.x == 0) {
        int run = 0;
        for (int j = 0; j < nb; j++) { int t = g_bsums[j]; g_boffs[j] = run; run += t; }
    }
}

__global__ void k_scan_add(int n, int total) {
    int i = blockIdx.x * blockDim.x + threadIdx.x;
    if (i < n) g_rowptr[i] += g_boffs[i >> 10];
    if (i == 0) g_rowptr[n] = total;
}

__global__ void k_place_self(int n) {
    int i = blockIdx.x * blockDim.x + threadIdx.x;
    if (i < n) {
        int p = g_rowptr[i];
        g_csr[p] = i;            // self loop edge first
        g_counts[i] = p + 1;     // cursor
    }
}

__global__ void k_scatter(const int* __restrict__ src, const int* __restrict__ dst, int e) {
    int i = blockIdx.x * blockDim.x + threadIdx.x;
    if (i < e) {
        int d = dst[i];
        int p = atomicAdd(&g_counts[d], 1);
        g_csr[p] = src[i];
    }
}

// ---------------- fused GEMM (h = X @ W) + per-node attention dots -----------
// blockDim = 128: tx = tid%64 (output column), tg = tid/64 (row-group 0/1);
// each thread accumulates 8 rows. Block covers 16 rows.
__global__ void k_gemm(const float* __restrict__ X, const float* __restrict__ W,
                       const float* __restrict__ avs, const float* __restrict__ avd,
                       float* __restrict__ Hout, int n) {
    __shared__ float W_s[64 * 64];
    __shared__ float x_s[16 * 64];
    __shared__ float as_s[64], ad_s[64];
    __shared__ float redA[4][8], redB[4][8];

    int tid = threadIdx.x;
    int tx = tid & 63;
    int tg = tid >> 6;
    int base = blockIdx.x * 16;

    for (int i = tid; i < 4096; i += 128) W_s[i] = W[i];
    if (tid < 64) { as_s[tid] = avs[tid]; ad_s[tid] = avd[tid]; }
    for (int i = tid; i < 1024; i += 128) {
        int r = i >> 6, k = i & 63;
        int gr = base + r;
        x_s[i] = (gr < n) ? X[gr * 64 + k] : 0.0f;
    }
    __syncthreads();

    float acc[8];
#pragma unroll
    for (int r = 0; r < 8; r++) acc[r] = 0.0f;

#pragma unroll
    for (int k = 0; k < 64; k++) {
        float w = W_s[k * 64 + tx];
#pragma unroll
        for (int r = 0; r < 8; r++)
            acc[r] += x_s[(tg * 8 + r) * 64 + k] * w;
    }

    // write h
#pragma unroll
    for (int r = 0; r < 8; r++) {
        int row = base + tg * 8 + r;
        if (row < n) Hout[row * 64 + tx] = acc[r];
    }

    // attention dots: asrc[row] = h_row . a_src, adst[row] = h_row . a_dst
    float pa[8], pb[8];
    float av = as_s[tx], bv = ad_s[tx];
#pragma unroll
    for (int r = 0; r < 8; r++) { pa[r] = acc[r] * av; pb[r] = acc[r] * bv; }
#pragma unroll
    for (int off = 16; off > 0; off >>= 1) {
#pragma unroll
        for (int r = 0; r < 8; r++) {
            pa[r] += __shfl_down_sync(0xFFFFFFFFu, pa[r], off);
            pb[r] += __shfl_down_sync(0xFFFFFFFFu, pb[r], off);
        }
    }
    int warp = tid >> 5;
    int lane = tid & 31;
    if (lane == 0) {
#pragma unroll
        for (int r = 0; r < 8; r++) { redA[warp][r] = pa[r]; redB[warp][r] = pb[r]; }
    }
    __syncthreads();
    if (tid < 16) {
        int g = tid >> 3, r = tid & 7;
        int row = base + g * 8 + r;
        if (row < n) {
            g_asrc[row] = redA[2 * g][r] + redA[2 * g + 1][r];
            g_adst[row] = redB[2 * g][r] + redB[2 * g + 1][r];
        }
    }
}

// ---------------- per-destination online-softmax aggregation -----------------
// one warp per destination node; acc kept as float2 per lane (64 floats/warp)
__global__ void k_agg(const float* __restrict__ Hsrc, const float* __restrict__ bias,
                      float* __restrict__ Hout, int n) {
    int warp = threadIdx.x >> 5;
    int lane = threadIdx.x & 31;
    int d = blockIdx.x * (blockDim.x >> 5) + warp;
    if (d >= n) return;

    float ad = g_adst[d];
    int beg = g_rowptr[d];
    int end = g_rowptr[d + 1];

    float m = -INFINITY, s = 0.0f, a0 = 0.0f, a1 = 0.0f;
    const float2* H2 = (const float2*)Hsrc;

    for (int j = beg; j < end; j++) {
        int sidx = g_csr[j];
        float l = g_asrc[sidx] + ad;
        l = (l > 0.0f) ? l : NEG_SLOPE * l;
        float2 hv = H2[sidx * 32 + lane];
        if (l > m) {
            float c = __expf(m - l);   // exp(-inf)=0 on first edge
            s *= c; a0 *= c; a1 *= c;
            m = l;
        }
        float w = __expf(l - m);
        s += w;
        a0 += w * hv.x;
        a1 += w * hv.y;
    }
    float inv = 1.0f / (s + 1e-16f);
    float o0 = a0 * inv + bias[2 * lane];
    float o1 = a1 * inv + bias[2 * lane + 1];
    o0 = fmaxf(o0, 0.0f);
    o1 = fmaxf(o1, 0.0f);
    ((float2*)Hout)[d * 32 + lane] = make_float2(o0, o1);
}

// ---------------- classifier + log_softmax (C = 2) ---------------------------
__global__ void k_classify(const float* __restrict__ H, const float* __restrict__ Wc,
                           const float* __restrict__ bc, float* __restrict__ out, int n) {
    int warp = threadIdx.x >> 5;
    int lane = threadIdx.x & 31;
    int i = blockIdx.x * (blockDim.x >> 5) + warp;
    if (i >= n) return;

    float2 hv = ((const float2*)H)[i * 32 + lane];
    float4 wv = ((const float4*)Wc)[lane];   // Wc[2*lane][0..1], Wc[2*lane+1][0..1]
    float p0 = hv.x * wv.x + hv.y * wv.z;
    float p1 = hv.x * wv.y + hv.y * wv.w;
#pragma unroll
    for (int off = 16; off > 0; off >>= 1) {
        p0 += __shfl_down_sync(0xFFFFFFFFu, p0, off);
        p1 += __shfl_down_sync(0xFFFFFFFFu, p1, off);
    }
    if (lane == 0) {
        float z0 = p0 + bc[0];
        float z1 = p1 + bc[1];
        float mx = fmaxf(z0, z1);
        float lse = mx + logf(expf(z0 - mx) + expf(z1 - mx));
        out[i * 2 + 0] = z0 - lse;
        out[i * 2 + 1] = z1 - lse;
    }
}

// ---------------- launch ------------------------------------------------------
extern "C" void kernel_launch(void* const* d_in, const int* in_sizes, int n_in,
                              void* d_out, int out_size) {
    const float* x      = (const float*)d_in[0];
    const int*   ei     = (const int*)d_in[1];
    const float* W1     = (const float*)d_in[2];
    const float* a_src1 = (const float*)d_in[3];
    const float* a_dst1 = (const float*)d_in[4];
    const float* b1     = (const float*)d_in[5];
    const float* W2     = (const float*)d_in[6];
    const float* a_src2 = (const float*)d_in[7];
    const float* a_dst2 = (const float*)d_in[8];
    const float* b2     = (const float*)d_in[9];
    const float* Wc     = (const float*)d_in[10];
    const float* bc     = (const float*)d_in[11];
    float* out = (float*)d_out;

    const int N = in_sizes[0] / F;
    const int E = in_sizes[1] / 2;
    const int* src = ei;
    const int* dst = ei + E;

    // ---- CSR build (dst-sorted edge list with self loops) ----
    k_init_counts<<<(N + 255) / 256, 256>>>(N);
    k_count<<<(E + 255) / 256, 256>>>(dst, E);
    int nb = (N + 1023) / 1024;
    k_scan_block<<<nb, 1024>>>(N);
    k_scan_sums<<<1, 32>>>(nb);
    k_scan_add<<<(N + 255) / 256, 256>>>(N, E + N);
    k_place_self<<<(N + 255) / 256, 256>>>(N);
    k_scatter<<<(E + 255) / 256, 256>>>(src, dst, E);

    // ---- layer 1 ----
    k_gemm<<<(N + 15) / 16, 128>>>(x, W1, a_src1, a_dst1, g_h, N);
    k_agg<<<(N + 7) / 8, 256>>>(g_h, b1, g_hagg, N);

    // ---- layer 2 ----
    k_gemm<<<(N + 15) / 16, 128>>>(g_hagg, W2, a_src2, a_dst2, g_h, N);
    k_agg<<<(N + 7) / 8, 256>>>(g_h, b2, g_hagg, N);

    // ---- classifier ----
    k_classify<<<(N + 7) / 8, 256>>>(g_hagg, Wc, bc, out, N);
}